// round 14
// baseline (speedup 1.0000x reference)
#include <cuda_runtime.h>
#include <cuda_bf16.h>
#include <cstdint>

#define Bsz 16
#define Cdim 512
#define HWp 4096
#define Sctx 77
#define CTXd 768
#define NHEADS 8
#define HD 64
#define NGROUPS 32
#define CPG 16
#define EPSV 1e-5f
#define NROWS (Bsz * Sctx)      // 1232
#define NROWS_PAD 1280

// ---- scratch (static device globals; no runtime allocation) ----
__device__ __nv_bfloat16 g_qb [(size_t)Bsz * Cdim * HWp]; // Q  (B, C, HW) bf16
__device__ __nv_bfloat16 g_xnb[(size_t)Bsz * Cdim * HWp]; // GN(x) bf16
__device__ __nv_bfloat16 g_aob[(size_t)Bsz * Cdim * HWp]; // attn out bf16
__device__ __nv_bfloat16 g_cnb[(size_t)NROWS_PAD * CTXd]; // layernormed ctx bf16 (padded)
__device__ __nv_bfloat16 g_kb [(size_t)NROWS * Cdim];     // K bf16 (n, C)
__device__ __nv_bfloat16 g_vb [(size_t)NROWS * Cdim];     // V bf16 (n, C)
__device__ __nv_bfloat16 g_qwb[Cdim * Cdim];              // q_w bf16
__device__ __nv_bfloat16 g_owb[Cdim * Cdim];              // out_w bf16
__device__ __nv_bfloat16 g_kwb[Cdim * CTXd];              // k_w bf16
__device__ __nv_bfloat16 g_vwb[Cdim * CTXd];              // v_w bf16

__device__ __forceinline__ uint32_t smem_u32(const void* p) {
    uint32_t a;
    asm("{ .reg .u64 t; cvta.to.shared.u64 t, %1; cvt.u32.u64 %0, t; }"
        : "=r"(a) : "l"(p));
    return a;
}
__device__ __forceinline__ uint32_t pack_bf16(float lo, float hi) {
    __nv_bfloat162 p = __floats2bfloat162_rn(lo, hi);
    return *reinterpret_cast<uint32_t*>(&p);
}
__device__ __forceinline__ void cp_async16(uint32_t dst, const void* src) {
    asm volatile("cp.async.cg.shared.global [%0], [%1], 16;"
                 :: "r"(dst), "l"(src));
}
__device__ __forceinline__ void cp_commit() {
    asm volatile("cp.async.commit_group;" ::: "memory");
}
template <int N>
__device__ __forceinline__ void cp_wait() {
    asm volatile("cp.async.wait_group %0;" :: "n"(N) : "memory");
}

// ============================================================
// Fused GroupNorm (monolithic): block per (b, g)
// ============================================================
__global__ void __launch_bounds__(512)
gn_fuse_kernel(const float* __restrict__ x,
               const float* __restrict__ gnw,
               const float* __restrict__ gnb) {
    int blk = blockIdx.x;
    int b = blk / NGROUPS, g = blk % NGROUPS;
    const size_t base = ((size_t)b * Cdim + (size_t)g * CPG) * HWp;
    const float4* p = (const float4*)(x + base);
    const int n4 = CPG * HWp / 4;  // 16384
    float s = 0.f, sq = 0.f;
    for (int i = threadIdx.x; i < n4; i += blockDim.x) {
        float4 v = p[i];
        s  += v.x + v.y + v.z + v.w;
        sq += v.x * v.x + v.y * v.y + v.z * v.z + v.w * v.w;
    }
    __shared__ float ss[32], ssq[32];
    __shared__ float sa[CPG], sb[CPG];
    #pragma unroll
    for (int o = 16; o > 0; o >>= 1) {
        s  += __shfl_down_sync(0xffffffffu, s, o);
        sq += __shfl_down_sync(0xffffffffu, sq, o);
    }
    int wid = threadIdx.x >> 5, lid = threadIdx.x & 31;
    if (lid == 0) { ss[wid] = s; ssq[wid] = sq; }
    __syncthreads();
    if (wid == 0) {
        int nw = blockDim.x >> 5;
        s  = (lid < nw) ? ss[lid]  : 0.f;
        sq = (lid < nw) ? ssq[lid] : 0.f;
        #pragma unroll
        for (int o = 16; o > 0; o >>= 1) {
            s  += __shfl_down_sync(0xffffffffu, s, o);
            sq += __shfl_down_sync(0xffffffffu, sq, o);
        }
        if (lid == 0) { ss[0] = s; ssq[0] = sq; }
    }
    __syncthreads();
    {
        const float invn = 1.f / (float)(CPG * HWp);
        float mean = ss[0] * invn;
        float var  = ssq[0] * invn - mean * mean;
        float rstd = rsqrtf(var + EPSV);
        if (threadIdx.x < CPG) {
            int c = g * CPG + threadIdx.x;
            float a = rstd * gnw[c];
            sa[threadIdx.x] = a;
            sb[threadIdx.x] = gnb[c] - mean * a;
        }
    }
    __syncthreads();
    __nv_bfloat162* dst = (__nv_bfloat162*)(g_xnb + base);
    const int per_c4 = HWp / 4;
    for (int i = threadIdx.x; i < n4; i += blockDim.x) {
        int c = i / per_c4;
        float a = sa[c], bb = sb[c];
        float4 v = p[i];
        dst[2 * i]     = __floats2bfloat162_rn(v.x * a + bb, v.y * a + bb);
        dst[2 * i + 1] = __floats2bfloat162_rn(v.z * a + bb, v.w * a + bb);
    }
}

// ============================================================
// LayerNorm on context -> bf16
// ============================================================
__global__ void ln_kernel(const float* __restrict__ ctx,
                          const float* __restrict__ w,
                          const float* __restrict__ bb) {
    int row = blockIdx.x;
    const float* xr = ctx + (size_t)row * CTXd;
    float s = 0.f, sq = 0.f;
    for (int i = threadIdx.x; i < CTXd; i += blockDim.x) {
        float v = xr[i];
        s += v; sq += v * v;
    }
    __shared__ float ss[32], ssq[32];
    __shared__ float smean, srstd;
    #pragma unroll
    for (int o = 16; o > 0; o >>= 1) {
        s  += __shfl_down_sync(0xffffffffu, s, o);
        sq += __shfl_down_sync(0xffffffffu, sq, o);
    }
    int wid = threadIdx.x >> 5, lid = threadIdx.x & 31;
    if (lid == 0) { ss[wid] = s; ssq[wid] = sq; }
    __syncthreads();
    if (wid == 0) {
        int nw = blockDim.x >> 5;
        s  = (lid < nw) ? ss[lid]  : 0.f;
        sq = (lid < nw) ? ssq[lid] : 0.f;
        #pragma unroll
        for (int o = 16; o > 0; o >>= 1) {
            s  += __shfl_down_sync(0xffffffffu, s, o);
            sq += __shfl_down_sync(0xffffffffu, sq, o);
        }
        if (lid == 0) {
            const float invn = 1.f / (float)CTXd;
            float mean = s * invn;
            float var  = sq * invn - mean * mean;
            smean = mean;
            srstd = rsqrtf(var + EPSV);
        }
    }
    __syncthreads();
    float mean = smean, rstd = srstd;
    for (int i = threadIdx.x; i < CTXd; i += blockDim.x) {
        g_cnb[(size_t)row * CTXd + i] =
            __float2bfloat16((xr[i] - mean) * rstd * w[i] + bb[i]);
    }
}

// ============================================================
// Weight bf16 conversion (q_w, out_w, k_w, v_w)
// ============================================================
#define NQW (Cdim * Cdim)
#define NKW (Cdim * CTXd)
__global__ void conv_w_kernel(const float* __restrict__ qw, const float* __restrict__ ow,
                              const float* __restrict__ kw, const float* __restrict__ vw) {
    int i = blockIdx.x * blockDim.x + threadIdx.x;
    if (i < NQW)                 g_qwb[i] = __float2bfloat16(qw[i]);
    else if (i < 2 * NQW)        g_owb[i - NQW] = __float2bfloat16(ow[i - NQW]);
    else if (i < 2 * NQW + NKW)  g_kwb[i - 2 * NQW] = __float2bfloat16(kw[i - 2 * NQW]);
    else                         g_vwb[i - 2 * NQW - NKW] = __float2bfloat16(vw[i - 2 * NQW - NKW]);
}

// ============================================================
// K/V projection via bf16 mma.sync (NT) — unchanged
// ============================================================
#define KVA_STR 40
#define KV_STAGE_BYTES (128 * KVA_STR * 2)
#define KV_STAGES 3
#define KV_NIT (CTXd / 32)

__global__ void __launch_bounds__(256, 2)
kv_mma(const float* __restrict__ kb_, const float* __restrict__ vb_) {
    __shared__ __align__(16) char smem_[KV_STAGES * 2 * KV_STAGE_BYTES];

    const __nv_bfloat16* W    = blockIdx.z ? g_vwb : g_kwb;
    const float*         bias = blockIdx.z ? vb_ : kb_;
    __nv_bfloat16*       out  = blockIdx.z ? g_vb : g_kb;

    const int tid  = threadIdx.x;
    const int warp = tid >> 5, lane = tid & 31;
    const int wm = warp >> 2, wn = warp & 3;
    const int n0 = blockIdx.y * 128;
    const int o0 = blockIdx.x * 128;

    const uint32_t sbase = smem_u32(smem_);
    const uint32_t sB0 = sbase + KV_STAGES * KV_STAGE_BYTES;

    const int ld_row = tid >> 2;
    const int ld_col = (tid & 3) * 8;

    const uint32_t st_off  = (ld_row * KVA_STR + ld_col) * 2;
    const uint32_t st_off2 = ((ld_row + 64) * KVA_STR + ld_col) * 2;

    const uint32_t a_lm_base =
        ((wm * 64 + (lane & 15)) * KVA_STR + (lane >> 4) * 8) * 2;
    const uint32_t b_lm_part =
        ((lane & 7) * KVA_STR + ((lane >> 3) & 1) * 8) * 2;

    float acc[4][4][4] = {};

    #pragma unroll
    for (int s = 0; s < KV_STAGES - 1; s++) {
        const int k0 = s * 32;
        uint32_t aS = sbase + s * KV_STAGE_BYTES;
        uint32_t bS = sB0 + s * KV_STAGE_BYTES;
        cp_async16(aS + st_off,  g_cnb + (size_t)(n0 + ld_row) * CTXd + k0 + ld_col);
        cp_async16(aS + st_off2, g_cnb + (size_t)(n0 + ld_row + 64) * CTXd + k0 + ld_col);
        cp_async16(bS + st_off,  W + (size_t)(o0 + ld_row) * CTXd + k0 + ld_col);
        cp_async16(bS + st_off2, W + (size_t)(o0 + ld_row + 64) * CTXd + k0 + ld_col);
        cp_commit();
    }

    #pragma unroll 1
    for (int it = 0; it < KV_NIT; it++) {
        cp_wait<KV_STAGES - 2>();
        __syncthreads();
        {
            const int sl = it + KV_STAGES - 1;
            if (sl < KV_NIT) {
                const int k0 = sl * 32;
                const int sb = sl % KV_STAGES;
                uint32_t aS = sbase + sb * KV_STAGE_BYTES;
                uint32_t bS = sB0 + sb * KV_STAGE_BYTES;
                cp_async16(aS + st_off,  g_cnb + (size_t)(n0 + ld_row) * CTXd + k0 + ld_col);
                cp_async16(aS + st_off2, g_cnb + (size_t)(n0 + ld_row + 64) * CTXd + k0 + ld_col);
                cp_async16(bS + st_off,  W + (size_t)(o0 + ld_row) * CTXd + k0 + ld_col);
                cp_async16(bS + st_off2, W + (size_t)(o0 + ld_row + 64) * CTXd + k0 + ld_col);
            }
            cp_commit();
        }

        const int sc = it % KV_STAGES;
        const uint32_t aBuf = sbase + sc * KV_STAGE_BYTES;
        const uint32_t bBuf = sB0 + sc * KV_STAGE_BYTES;

        #pragma unroll
        for (int kk = 0; kk < 2; kk++) {
            uint32_t af[4][4];
            #pragma unroll
            for (int mt = 0; mt < 4; mt++) {
                uint32_t addr = aBuf + a_lm_base + (mt * 16 * KVA_STR + kk * 16) * 2;
                asm volatile(
                    "ldmatrix.sync.aligned.m8n8.x4.shared.b16 {%0,%1,%2,%3}, [%4];"
                    : "=r"(af[mt][0]), "=r"(af[mt][1]), "=r"(af[mt][2]), "=r"(af[mt][3])
                    : "r"(addr));
            }
            uint32_t bf[4][2];
            #pragma unroll
            for (int nt = 0; nt < 4; nt++) {
                uint32_t addr = bBuf + b_lm_part +
                    (((wn * 32 + nt * 8) * KVA_STR) + kk * 16) * 2;
                asm volatile(
                    "ldmatrix.sync.aligned.m8n8.x2.shared.b16 {%0,%1}, [%2];"
                    : "=r"(bf[nt][0]), "=r"(bf[nt][1]) : "r"(addr));
            }
            #pragma unroll
            for (int mt = 0; mt < 4; mt++)
                #pragma unroll
                for (int nt = 0; nt < 4; nt++) {
                    asm volatile(
                        "mma.sync.aligned.m16n8k16.row.col.f32.bf16.bf16.f32 "
                        "{%0,%1,%2,%3}, {%4,%5,%6,%7}, {%8,%9}, {%0,%1,%2,%3};"
                        : "+f"(acc[mt][nt][0]), "+f"(acc[mt][nt][1]),
                          "+f"(acc[mt][nt][2]), "+f"(acc[mt][nt][3])
                        : "r"(af[mt][0]), "r"(af[mt][1]), "r"(af[mt][2]), "r"(af[mt][3]),
                          "r"(bf[nt][0]), "r"(bf[nt][1]));
                }
        }
    }

    const int row_base = n0 + wm * 64 + (lane >> 2);
    const int col_base = o0 + wn * 32 + (lane & 3) * 2;
    #pragma unroll
    for (int mt = 0; mt < 4; mt++) {
        #pragma unroll
        for (int half = 0; half < 2; half++) {
            int row = row_base + mt * 16 + half * 8;
            if (row >= NROWS) continue;
            #pragma unroll
            for (int nt = 0; nt < 4; nt++) {
                int col = col_base + nt * 8;
                float bi0 = bias[col], bi1 = bias[col + 1];
                *(__nv_bfloat162*)(out + (size_t)row * Cdim + col) =
                    __floats2bfloat162_rn(acc[mt][nt][half * 2] + bi0,
                                          acc[mt][nt][half * 2 + 1] + bi1);
            }
        }
    }
}

// ============================================================
// bf16 mma.sync GEMM — 128 thr / 4 warps, warp tile 64x64,
// B fragments via x4.trans ldmatrix. 5-stage cp.async pipeline.
// ============================================================
#define A_STRIDE 40
#define B_STRIDE 136
#define STAGES 5
#define A_STAGE_BYTES (128 * A_STRIDE * 2)
#define B_STAGE_BYTES (32 * B_STRIDE * 2)
#define NIT (Cdim / 32)

template <bool BF16OUT>
__global__ void __launch_bounds__(128, 2)
mma_gemm(const __nv_bfloat16* __restrict__ Wb,
         const __nv_bfloat16* __restrict__ Xb,
         const float* __restrict__ bias,
         const float* __restrict__ residual,
         void* __restrict__ outv,
         int b0) {
    __shared__ __align__(16) char smem_[STAGES * (A_STAGE_BYTES + B_STAGE_BYTES)];

    const int tid  = threadIdx.x;
    const int warp = tid >> 5, lane = tid & 31;
    const int wm = warp >> 1, wn = warp & 1;
    const int p0 = blockIdx.x * 128;
    const int o0 = blockIdx.y * 128;
    const int b  = b0 + blockIdx.z;
    const __nv_bfloat16* Xbb = Xb + (size_t)b * Cdim * HWp;

    const uint32_t sbase = smem_u32(smem_);
    const uint32_t sB0 = sbase + STAGES * A_STAGE_BYTES;

    const int a_ld_row = tid >> 2;
    const int a_ld_col = (tid & 3) * 8;
    const int b_ld_row = tid >> 4;
    const int b_ld_col = (tid & 15) * 8;

    const uint32_t a_lm_base =
        ((wm * 64 + (lane & 15)) * A_STRIDE + (lane >> 4) * 8) * 2;
    const uint32_t b_lm4_base =
        (((lane & 7) + ((lane >> 3) & 1) * 8) * B_STRIDE +
         wn * 64 + ((lane >> 4) & 1) * 8) * 2;

    uint32_t a_st[4], b_st[4];
    #pragma unroll
    for (int j = 0; j < 4; j++) {
        a_st[j] = ((a_ld_row + j * 32) * A_STRIDE + a_ld_col) * 2;
        b_st[j] = ((b_ld_row + j * 8) * B_STRIDE + b_ld_col) * 2;
    }

    float acc[4][8][4] = {};

    #pragma unroll
    for (int s = 0; s < STAGES - 1; s++) {
        const int k0 = s * 32;
        uint32_t aS = sbase + s * A_STAGE_BYTES;
        uint32_t bS = sB0 + s * B_STAGE_BYTES;
        #pragma unroll
        for (int j = 0; j < 4; j++) {
            cp_async16(aS + a_st[j],
                       Wb + (size_t)(o0 + a_ld_row + j * 32) * Cdim + k0 + a_ld_col);
            cp_async16(bS + b_st[j],
                       Xbb + (size_t)(k0 + b_ld_row + j * 8) * HWp + p0 + b_ld_col);
        }
        cp_commit();
    }

    #pragma unroll 1
    for (int it = 0; it < NIT; it++) {
        cp_wait<STAGES - 2>();
        __syncthreads();
        {
            const int sl = it + STAGES - 1;
            if (sl < NIT) {
                const int k0 = sl * 32;
                const int sb = sl % STAGES;
                uint32_t aS = sbase + sb * A_STAGE_BYTES;
                uint32_t bS = sB0 + sb * B_STAGE_BYTES;
                #pragma unroll
                for (int j = 0; j < 4; j++) {
                    cp_async16(aS + a_st[j],
                               Wb + (size_t)(o0 + a_ld_row + j * 32) * Cdim + k0 + a_ld_col);
                    cp_async16(bS + b_st[j],
                               Xbb + (size_t)(k0 + b_ld_row + j * 8) * HWp + p0 + b_ld_col);
                }
            }
            cp_commit();
        }

        const int sc = it % STAGES;
        const uint32_t aBuf = sbase + sc * A_STAGE_BYTES;
        const uint32_t bBuf = sB0 + sc * B_STAGE_BYTES;

        #pragma unroll
        for (int kk = 0; kk < 2; kk++) {
            uint32_t af[4][4];
            #pragma unroll
            for (int mt = 0; mt < 4; mt++) {
                uint32_t addr = aBuf + a_lm_base + (mt * 16 * A_STRIDE + kk * 16) * 2;
                asm volatile(
                    "ldmatrix.sync.aligned.m8n8.x4.shared.b16 {%0,%1,%2,%3}, [%4];"
                    : "=r"(af[mt][0]), "=r"(af[mt][1]), "=r"(af[mt][2]), "=r"(af[mt][3])
                    : "r"(addr));
            }
            uint32_t bf[8][2];
            #pragma unroll
            for (int ntp = 0; ntp < 4; ntp++) {
                uint32_t addr = bBuf + b_lm4_base +
                    (kk * 16 * B_STRIDE + ntp * 16) * 2;
                asm volatile(
                    "ldmatrix.sync.aligned.m8n8.x4.trans.shared.b16 {%0,%1,%2,%3}, [%4];"
                    : "=r"(bf[2 * ntp][0]), "=r"(bf[2 * ntp][1]),
                      "=r"(bf[2 * ntp + 1][0]), "=r"(bf[2 * ntp + 1][1])
                    : "r"(addr));
            }
            #pragma unroll
            for (int mt = 0; mt < 4; mt++)
                #pragma unroll
                for (int nt = 0; nt < 8; nt++) {
                    asm volatile(
                        "mma.sync.aligned.m16n8k16.row.col.f32.bf16.bf16.f32 "
                        "{%0,%1,%2,%3}, {%4,%5,%6,%7}, {%8,%9}, {%0,%1,%2,%3};"
                        : "+f"(acc[mt][nt][0]), "+f"(acc[mt][nt][1]),
                          "+f"(acc[mt][nt][2]), "+f"(acc[mt][nt][3])
                        : "r"(af[mt][0]), "r"(af[mt][1]), "r"(af[mt][2]), "r"(af[mt][3]),
                          "r"(bf[nt][0]), "r"(bf[nt][1]));
                }
        }
    }

    const int row_base = o0 + wm * 64 + (lane >> 2);
    const int col_base = p0 + wn * 64 + (lane & 3) * 2;
    #pragma unroll
    for (int mt = 0; mt < 4; mt++) {
        #pragma unroll
        for (int half = 0; half < 2; half++) {
            int row = row_base + mt * 16 + half * 8;
            float bi = bias[row];
            size_t rb = ((size_t)b * Cdim + row) * HWp;
            #pragma unroll
            for (int nt = 0; nt < 8; nt++) {
                int col = col_base + nt * 8;
                float rx = acc[mt][nt][half * 2]     + bi;
                float ry = acc[mt][nt][half * 2 + 1] + bi;
                if (BF16OUT) {
                    __nv_bfloat16* outb = (__nv_bfloat16*)outv;
                    *(__nv_bfloat162*)(outb + rb + col) = __floats2bfloat162_rn(rx, ry);
                } else {
                    float* outf = (float*)outv;
                    if (residual) {
                        float2 rv = *(const float2*)(residual + rb + col);
                        rx += rv.x; ry += rv.y;
                    }
                    float2 r; r.x = rx; r.y = ry;
                    *(float2*)(outf + rb + col) = r;
                }
            }
        }
    }
}

// ============================================================
// Tensor-core flash attention — monolithic (unchanged from R13)
// ============================================================
#define QS_STR 136
#define KS_STR 72
#define SPAD 80

__global__ void __launch_bounds__(128)
attn_mma_kernel() {
    __shared__ __align__(16) __nv_bfloat16 sQ[64 * QS_STR];
    __shared__ __align__(16) __nv_bfloat16 sK[SPAD * KS_STR];
    __shared__ __align__(16) __nv_bfloat16 sV[SPAD * KS_STR];

    const int tid = threadIdx.x;
    const int warp = tid >> 5, lane = tid & 31;
    const int b = blockIdx.z, h = blockIdx.y;
    const int p0 = blockIdx.x * 128;
    const int ch0 = h * HD;

    const __nv_bfloat16* qg = g_qb + ((size_t)b * Cdim + ch0) * HWp + p0;
    #pragma unroll 4
    for (int i = tid; i < 64 * 16; i += 128) {
        int d = i >> 4, cc = (i & 15) * 8;
        *(uint4*)(sQ + d * QS_STR + cc) = *(const uint4*)(qg + (size_t)d * HWp + cc);
    }
    const __nv_bfloat16* kg = g_kb + (size_t)b * Sctx * Cdim + ch0;
    for (int i = tid; i < 77 * 8; i += 128) {
        int s = i >> 3, dd = (i & 7) * 8;
        *(uint4*)(sK + s * KS_STR + dd) = *(const uint4*)(kg + (size_t)s * Cdim + dd);
    }
    if (tid < 24) {
        int s = 77 + tid / 8, dd = (tid & 7) * 8;
        uint4 z = {0, 0, 0, 0};
        *(uint4*)(sK + s * KS_STR + dd) = z;
    }
    const __nv_bfloat16* vg = g_vb + (size_t)b * Sctx * Cdim + ch0;
    for (int i = tid; i < 77 * 8; i += 128) {
        int s = i >> 3, dd = (i & 7) * 8;
        *(uint4*)(sV + s * KS_STR + dd) = *(const uint4*)(vg + (size_t)s * Cdim + dd);
    }
    if (tid >= 104) {
        int t = tid - 104;
        int s = 77 + t / 8, dd = (t & 7) * 8;
        uint4 z = {0, 0, 0, 0};
        *(uint4*)(sV + s * KS_STR + dd) = z;
    }
    __syncthreads();

    const uint32_t qbase = smem_u32(sQ);
    const uint32_t kbase = smem_u32(sK);
    const uint32_t vbase = smem_u32(sV);

    float c[2][10][4];
    #pragma unroll
    for (int mt = 0; mt < 2; mt++)
        #pragma unroll
        for (int nt = 0; nt < 10; nt++)
            #pragma unroll
            for (int r = 0; r < 4; r++) c[mt][nt][r] = 0.f;

    const int a_krow = ((lane >> 4) & 1) * 8 + (lane & 7);
    const int a_mcol = ((lane >> 3) & 1) * 8;
    const uint32_t b_lm_part = ((lane & 7) * KS_STR + ((lane >> 3) & 1) * 8) * 2;

    #pragma unroll
    for (int kk = 0; kk < 4; kk++) {
        uint32_t af[2][4];
        #pragma unroll
        for (int mt = 0; mt < 2; mt++) {
            uint32_t addr = qbase +
                ((kk * 16 + a_krow) * QS_STR + warp * 32 + mt * 16 + a_mcol) * 2;
            asm volatile(
                "ldmatrix.sync.aligned.m8n8.x4.trans.shared.b16 {%0,%1,%2,%3}, [%4];"
                : "=r"(af[mt][0]), "=r"(af[mt][1]), "=r"(af[mt][2]), "=r"(af[mt][3])
                : "r"(addr));
        }
        uint32_t bf[10][2];
        #pragma unroll
        for (int nt = 0; nt < 10; nt++) {
            uint32_t addr = kbase + b_lm_part + ((nt * 8) * KS_STR + kk * 16) * 2;
            asm volatile(
                "ldmatrix.sync.aligned.m8n8.x2.shared.b16 {%0,%1}, [%2];"
                : "=r"(bf[nt][0]), "=r"(bf[nt][1]) : "r"(addr));
        }
        #pragma unroll
        for (int mt = 0; mt < 2; mt++)
            #pragma unroll
            for (int nt = 0; nt < 10; nt++) {
                asm volatile(
                    "mma.sync.aligned.m16n8k16.row.col.f32.bf16.bf16.f32 "
                    "{%0,%1,%2,%3}, {%4,%5,%6,%7}, {%8,%9}, {%0,%1,%2,%3};"
                    : "+f"(c[mt][nt][0]), "+f"(c[mt][nt][1]),
                      "+f"(c[mt][nt][2]), "+f"(c[mt][nt][3])
                    : "r"(af[mt][0]), "r"(af[mt][1]), "r"(af[mt][2]), "r"(af[mt][3]),
                      "r"(bf[nt][0]), "r"(bf[nt][1]));
            }
    }
    __syncthreads();

    const float scale = 0.125f;
    uint32_t pu[2][10][2];
    float iv[2][2];
    #pragma unroll
    for (int mt = 0; mt < 2; mt++) {
        float mx0 = -1e30f, mx1 = -1e30f;
        #pragma unroll
        for (int nt = 0; nt < 10; nt++) {
            int col = nt * 8 + (lane & 3) * 2;
            c[mt][nt][0] = (col     < Sctx) ? c[mt][nt][0] * scale : -1e30f;
            c[mt][nt][1] = (col + 1 < Sctx) ? c[mt][nt][1] * scale : -1e30f;
            c[mt][nt][2] = (col     < Sctx) ? c[mt][nt][2] * scale : -1e30f;
            c[mt][nt][3] = (col + 1 < Sctx) ? c[mt][nt][3] * scale : -1e30f;
            mx0 = fmaxf(mx0, fmaxf(c[mt][nt][0], c[mt][nt][1]));
            mx1 = fmaxf(mx1, fmaxf(c[mt][nt][2], c[mt][nt][3]));
        }
        mx0 = fmaxf(mx0, __shfl_xor_sync(0xffffffffu, mx0, 1));
        mx0 = fmaxf(mx0, __shfl_xor_sync(0xffffffffu, mx0, 2));
        mx1 = fmaxf(mx1, __shfl_xor_sync(0xffffffffu, mx1, 1));
        mx1 = fmaxf(mx1, __shfl_xor_sync(0xffffffffu, mx1, 2));
        float s0 = 0.f, s1 = 0.f;
        #pragma unroll
        for (int nt = 0; nt < 10; nt++) {
            float e0 = __expf(c[mt][nt][0] - mx0);
            float e1 = __expf(c[mt][nt][1] - mx0);
            float e2 = __expf(c[mt][nt][2] - mx1);
            float e3 = __expf(c[mt][nt][3] - mx1);
            s0 += e0 + e1; s1 += e2 + e3;
            pu[mt][nt][0] = pack_bf16(e0, e1);
            pu[mt][nt][1] = pack_bf16(e2, e3);
        }
        s0 += __shfl_xor_sync(0xffffffffu, s0, 1);
        s0 += __shfl_xor_sync(0xffffffffu, s0, 2);
        s1 += __shfl_xor_sync(0xffffffffu, s1, 1);
        s1 += __shfl_xor_sync(0xffffffffu, s1, 2);
        iv[mt][0] = 1.f / s0;
        iv[mt][1] = 1.f / s1;
    }

    float o[2][8][4];
    #pragma unroll
    for (int mt = 0; mt < 2; mt++)
        #pragma unroll
        for (int nt = 0; nt < 8; nt++)
            #pragma unroll
            for (int r = 0; r < 4; r++) o[mt][nt][r] = 0.f;

    #pragma unroll
    for (int kk = 0; kk < 5; kk++) {
        uint32_t bv[8][2];
        #pragma unroll
        for (int nt = 0; nt < 8; nt++) {
            uint32_t addr = vbase + ((kk * 16 + (lane & 15)) * KS_STR + nt * 8) * 2;
            asm volatile(
                "ldmatrix.sync.aligned.m8n8.x2.trans.shared.b16 {%0,%1}, [%2];"
                : "=r"(bv[nt][0]), "=r"(bv[nt][1]) : "r"(addr));
        }
        #pragma unroll
        for (int mt = 0; mt < 2; mt++) {
            uint32_t a0 = pu[mt][2 * kk][0];
            uint32_t a1 = pu[mt][2 * kk][1];
            uint32_t a2 = pu[mt][2 * kk + 1][0];
            uint32_t a3 = pu[mt][2 * kk + 1][1];
            #pragma unroll
            for (int nt = 0; nt < 8; nt++) {
                asm volatile(
                    "mma.sync.aligned.m16n8k16.row.col.f32.bf16.bf16.f32 "
                    "{%0,%1,%2,%3}, {%4,%5,%6,%7}, {%8,%9}, {%0,%1,%2,%3};"
                    : "+f"(o[mt][nt][0]), "+f"(o[mt][nt][1]),
                      "+f"(o[mt][nt][2]), "+f"(o[mt][nt][3])
                    : "r"(a0), "r"(a1), "r"(a2), "r"(a3),
                      "r"(bv[nt][0]), "r"(bv[nt][1]));
            }
        }
    }

    __nv_bfloat16* Od = sQ;
    #pragma unroll
    for (int mt = 0; mt < 2; mt++) {
        int pxa = warp * 32 + mt * 16 + (lane >> 2);
        #pragma unroll
        for (int nt = 0; nt < 8; nt++) {
            int d = nt * 8 + (lane & 3) * 2;
            Od[d * QS_STR + pxa]           = __float2bfloat16(o[mt][nt][0] * iv[mt][0]);
            Od[(d + 1) * QS_STR + pxa]     = __float2bfloat16(o[mt][nt][1] * iv[mt][0]);
            Od[d * QS_STR + pxa + 8]       = __float2bfloat16(o[mt][nt][2] * iv[mt][1]);
            Od[(d + 1) * QS_STR + pxa + 8] = __float2bfloat16(o[mt][nt][3] * iv[mt][1]);
        }
    }
    __syncthreads();

    __nv_bfloat16* og = g_aob + ((size_t)b * Cdim + ch0) * HWp + p0;
    #pragma unroll 2
    for (int i = tid; i < 64 * 16; i += 128) {
        int d = i >> 4, cc = (i & 15) * 8;
        *(uint4*)(og + (size_t)d * HWp + cc) = *(const uint4*)(Od + d * QS_STR + cc);
    }
}

// ============================================================
extern "C" void kernel_launch(void* const* d_in, const int* in_sizes, int n_in,
                              void* d_out, int out_size) {
    const float* x       = (const float*)d_in[0];
    const float* context = (const float*)d_in[1];
    const float* gn_w    = (const float*)d_in[2];
    const float* gn_b    = (const float*)d_in[3];
    const float* ln_w    = (const float*)d_in[4];
    const float* ln_b    = (const float*)d_in[5];
    const float* q_w     = (const float*)d_in[6];
    const float* q_b     = (const float*)d_in[7];
    const float* k_w     = (const float*)d_in[8];
    const float* k_b     = (const float*)d_in[9];
    const float* v_w     = (const float*)d_in[10];
    const float* v_b     = (const float*)d_in[11];
    const float* out_w   = (const float*)d_in[12];
    const float* out_b   = (const float*)d_in[13];
    float* out = (float*)d_out;

    __nv_bfloat16 *qb = nullptr, *xnb = nullptr, *aob = nullptr, *qwb = nullptr, *owb = nullptr;
    cudaGetSymbolAddress((void**)&qb,  g_qb);
    cudaGetSymbolAddress((void**)&xnb, g_xnb);
    cudaGetSymbolAddress((void**)&aob, g_aob);
    cudaGetSymbolAddress((void**)&qwb, g_qwb);
    cudaGetSymbolAddress((void**)&owb, g_owb);

    // one-time side stream + events (created on the uncaptured correctness call)
    static cudaStream_t s_side = nullptr;
    static cudaEvent_t ev_fork = nullptr, ev_w = nullptr, ev_kv = nullptr;
    if (s_side == nullptr) {
        cudaStreamCreateWithFlags(&s_side, cudaStreamNonBlocking);
        cudaEventCreateWithFlags(&ev_fork, cudaEventDisableTiming);
        cudaEventCreateWithFlags(&ev_w,    cudaEventDisableTiming);
        cudaEventCreateWithFlags(&ev_kv,   cudaEventDisableTiming);
    }

    // fork side stream
    cudaEventRecord(ev_fork, 0);
    cudaStreamWaitEvent(s_side, ev_fork, 0);

    // side chain: weights -> ln -> kv
    conv_w_kernel<<<(2 * NQW + 2 * NKW) / 512, 512, 0, s_side>>>(q_w, out_w, k_w, v_w);
    cudaEventRecord(ev_w, s_side);
    ln_kernel<<<Bsz * Sctx, 256, 0, s_side>>>(context, ln_w, ln_b);
    kv_mma<<<dim3(Cdim / 128, NROWS_PAD / 128, 2), 256, 0, s_side>>>(k_b, v_b);
    cudaEventRecord(ev_kv, s_side);

    // main chain: gn (monolithic) -> qproj -> attn -> outproj
    gn_fuse_kernel<<<Bsz * NGROUPS, 512>>>(x, gn_w, gn_b);
    cudaStreamWaitEvent(0, ev_w, 0);
    mma_gemm<true><<<dim3(HWp / 128, Cdim / 128, Bsz), 128>>>(
        qwb, xnb, q_b, nullptr, qb, 0);
    cudaStreamWaitEvent(0, ev_kv, 0);
    attn_mma_kernel<<<dim3(HWp / 128, NHEADS, Bsz), 128>>>();
    mma_gemm<false><<<dim3(HWp / 128, Cdim / 128, Bsz), 128>>>(
        owb, aob, out_b, x, out, 0);
}

// round 15
// speedup vs baseline: 1.4525x; 1.4525x over previous
#include <cuda_runtime.h>
#include <cuda_bf16.h>
#include <cstdint>

#define Bsz 16
#define Cdim 512
#define HWp 4096
#define Sctx 77
#define CTXd 768
#define NHEADS 8
#define HD 64
#define NGROUPS 32
#define CPG 16
#define EPSV 1e-5f
#define NROWS (Bsz * Sctx)      // 1232
#define NROWS_PAD 1280

// ---- scratch (static device globals; no runtime allocation) ----
__device__ __nv_bfloat16 g_qb [(size_t)Bsz * Cdim * HWp]; // Q  (B, C, HW) bf16
__device__ __nv_bfloat16 g_xnb[(size_t)Bsz * Cdim * HWp]; // GN(x) bf16
__device__ __nv_bfloat16 g_aob[(size_t)Bsz * Cdim * HWp]; // attn out bf16
__device__ __nv_bfloat16 g_cnb[(size_t)NROWS_PAD * CTXd]; // layernormed ctx bf16 (padded)
__device__ __nv_bfloat16 g_kb [(size_t)NROWS * Cdim];     // K bf16 (n, C)
__device__ __nv_bfloat16 g_vb [(size_t)NROWS * Cdim];     // V bf16 (n, C)
__device__ __nv_bfloat16 g_qwb[Cdim * Cdim];              // q_w bf16
__device__ __nv_bfloat16 g_owb[Cdim * Cdim];              // out_w bf16
__device__ __nv_bfloat16 g_kwb[Cdim * CTXd];              // k_w bf16
__device__ __nv_bfloat16 g_vwb[Cdim * CTXd];              // v_w bf16

__device__ __forceinline__ uint32_t smem_u32(const void* p) {
    uint32_t a;
    asm("{ .reg .u64 t; cvta.to.shared.u64 t, %1; cvt.u32.u64 %0, t; }"
        : "=r"(a) : "l"(p));
    return a;
}
__device__ __forceinline__ uint32_t pack_bf16(float lo, float hi) {
    __nv_bfloat162 p = __floats2bfloat162_rn(lo, hi);
    return *reinterpret_cast<uint32_t*>(&p);
}
__device__ __forceinline__ void cp_async16(uint32_t dst, const void* src) {
    asm volatile("cp.async.cg.shared.global [%0], [%1], 16;"
                 :: "r"(dst), "l"(src));
}
__device__ __forceinline__ void cp_commit() {
    asm volatile("cp.async.commit_group;" ::: "memory");
}
template <int N>
__device__ __forceinline__ void cp_wait() {
    asm volatile("cp.async.wait_group %0;" :: "n"(N) : "memory");
}

// ============================================================
// Fused GroupNorm (monolithic): block per (b, g)
// ============================================================
__global__ void __launch_bounds__(512)
gn_fuse_kernel(const float* __restrict__ x,
               const float* __restrict__ gnw,
               const float* __restrict__ gnb) {
    int blk = blockIdx.x;
    int b = blk / NGROUPS, g = blk % NGROUPS;
    const size_t base = ((size_t)b * Cdim + (size_t)g * CPG) * HWp;
    const float4* p = (const float4*)(x + base);
    const int n4 = CPG * HWp / 4;  // 16384
    float s = 0.f, sq = 0.f;
    for (int i = threadIdx.x; i < n4; i += blockDim.x) {
        float4 v = p[i];
        s  += v.x + v.y + v.z + v.w;
        sq += v.x * v.x + v.y * v.y + v.z * v.z + v.w * v.w;
    }
    __shared__ float ss[32], ssq[32];
    __shared__ float sa[CPG], sb[CPG];
    #pragma unroll
    for (int o = 16; o > 0; o >>= 1) {
        s  += __shfl_down_sync(0xffffffffu, s, o);
        sq += __shfl_down_sync(0xffffffffu, sq, o);
    }
    int wid = threadIdx.x >> 5, lid = threadIdx.x & 31;
    if (lid == 0) { ss[wid] = s; ssq[wid] = sq; }
    __syncthreads();
    if (wid == 0) {
        int nw = blockDim.x >> 5;
        s  = (lid < nw) ? ss[lid]  : 0.f;
        sq = (lid < nw) ? ssq[lid] : 0.f;
        #pragma unroll
        for (int o = 16; o > 0; o >>= 1) {
            s  += __shfl_down_sync(0xffffffffu, s, o);
            sq += __shfl_down_sync(0xffffffffu, sq, o);
        }
        if (lid == 0) { ss[0] = s; ssq[0] = sq; }
    }
    __syncthreads();
    {
        const float invn = 1.f / (float)(CPG * HWp);
        float mean = ss[0] * invn;
        float var  = ssq[0] * invn - mean * mean;
        float rstd = rsqrtf(var + EPSV);
        if (threadIdx.x < CPG) {
            int c = g * CPG + threadIdx.x;
            float a = rstd * gnw[c];
            sa[threadIdx.x] = a;
            sb[threadIdx.x] = gnb[c] - mean * a;
        }
    }
    __syncthreads();
    __nv_bfloat162* dst = (__nv_bfloat162*)(g_xnb + base);
    const int per_c4 = HWp / 4;
    for (int i = threadIdx.x; i < n4; i += blockDim.x) {
        int c = i / per_c4;
        float a = sa[c], bb = sb[c];
        float4 v = p[i];
        dst[2 * i]     = __floats2bfloat162_rn(v.x * a + bb, v.y * a + bb);
        dst[2 * i + 1] = __floats2bfloat162_rn(v.z * a + bb, v.w * a + bb);
    }
}

// ============================================================
// LayerNorm on context -> bf16
// ============================================================
__global__ void ln_kernel(const float* __restrict__ ctx,
                          const float* __restrict__ w,
                          const float* __restrict__ bb) {
    int row = blockIdx.x;
    const float* xr = ctx + (size_t)row * CTXd;
    float s = 0.f, sq = 0.f;
    for (int i = threadIdx.x; i < CTXd; i += blockDim.x) {
        float v = xr[i];
        s += v; sq += v * v;
    }
    __shared__ float ss[32], ssq[32];
    __shared__ float smean, srstd;
    #pragma unroll
    for (int o = 16; o > 0; o >>= 1) {
        s  += __shfl_down_sync(0xffffffffu, s, o);
        sq += __shfl_down_sync(0xffffffffu, sq, o);
    }
    int wid = threadIdx.x >> 5, lid = threadIdx.x & 31;
    if (lid == 0) { ss[wid] = s; ssq[wid] = sq; }
    __syncthreads();
    if (wid == 0) {
        int nw = blockDim.x >> 5;
        s  = (lid < nw) ? ss[lid]  : 0.f;
        sq = (lid < nw) ? ssq[lid] : 0.f;
        #pragma unroll
        for (int o = 16; o > 0; o >>= 1) {
            s  += __shfl_down_sync(0xffffffffu, s, o);
            sq += __shfl_down_sync(0xffffffffu, sq, o);
        }
        if (lid == 0) {
            const float invn = 1.f / (float)CTXd;
            float mean = s * invn;
            float var  = sq * invn - mean * mean;
            smean = mean;
            srstd = rsqrtf(var + EPSV);
        }
    }
    __syncthreads();
    float mean = smean, rstd = srstd;
    for (int i = threadIdx.x; i < CTXd; i += blockDim.x) {
        g_cnb[(size_t)row * CTXd + i] =
            __float2bfloat16((xr[i] - mean) * rstd * w[i] + bb[i]);
    }
}

// ============================================================
// Weight bf16 conversion (q_w, out_w, k_w, v_w)
// ============================================================
#define NQW (Cdim * Cdim)
#define NKW (Cdim * CTXd)
__global__ void conv_w_kernel(const float* __restrict__ qw, const float* __restrict__ ow,
                              const float* __restrict__ kw, const float* __restrict__ vw) {
    int i = blockIdx.x * blockDim.x + threadIdx.x;
    if (i < NQW)                 g_qwb[i] = __float2bfloat16(qw[i]);
    else if (i < 2 * NQW)        g_owb[i - NQW] = __float2bfloat16(ow[i - NQW]);
    else if (i < 2 * NQW + NKW)  g_kwb[i - 2 * NQW] = __float2bfloat16(kw[i - 2 * NQW]);
    else                         g_vwb[i - 2 * NQW - NKW] = __float2bfloat16(vw[i - 2 * NQW - NKW]);
}

// ============================================================
// K/V projection via bf16 mma.sync (NT) — unchanged
// ============================================================
#define KVA_STR 40
#define KV_STAGE_BYTES (128 * KVA_STR * 2)
#define KV_STAGES 3
#define KV_NIT (CTXd / 32)

__global__ void __launch_bounds__(256, 2)
kv_mma(const float* __restrict__ kb_, const float* __restrict__ vb_) {
    __shared__ __align__(16) char smem_[KV_STAGES * 2 * KV_STAGE_BYTES];

    const __nv_bfloat16* W    = blockIdx.z ? g_vwb : g_kwb;
    const float*         bias = blockIdx.z ? vb_ : kb_;
    __nv_bfloat16*       out  = blockIdx.z ? g_vb : g_kb;

    const int tid  = threadIdx.x;
    const int warp = tid >> 5, lane = tid & 31;
    const int wm = warp >> 2, wn = warp & 3;
    const int n0 = blockIdx.y * 128;
    const int o0 = blockIdx.x * 128;

    const uint32_t sbase = smem_u32(smem_);
    const uint32_t sB0 = sbase + KV_STAGES * KV_STAGE_BYTES;

    const int ld_row = tid >> 2;
    const int ld_col = (tid & 3) * 8;

    const uint32_t st_off  = (ld_row * KVA_STR + ld_col) * 2;
    const uint32_t st_off2 = ((ld_row + 64) * KVA_STR + ld_col) * 2;

    const uint32_t a_lm_base =
        ((wm * 64 + (lane & 15)) * KVA_STR + (lane >> 4) * 8) * 2;
    const uint32_t b_lm_part =
        ((lane & 7) * KVA_STR + ((lane >> 3) & 1) * 8) * 2;

    float acc[4][4][4] = {};

    #pragma unroll
    for (int s = 0; s < KV_STAGES - 1; s++) {
        const int k0 = s * 32;
        uint32_t aS = sbase + s * KV_STAGE_BYTES;
        uint32_t bS = sB0 + s * KV_STAGE_BYTES;
        cp_async16(aS + st_off,  g_cnb + (size_t)(n0 + ld_row) * CTXd + k0 + ld_col);
        cp_async16(aS + st_off2, g_cnb + (size_t)(n0 + ld_row + 64) * CTXd + k0 + ld_col);
        cp_async16(bS + st_off,  W + (size_t)(o0 + ld_row) * CTXd + k0 + ld_col);
        cp_async16(bS + st_off2, W + (size_t)(o0 + ld_row + 64) * CTXd + k0 + ld_col);
        cp_commit();
    }

    #pragma unroll 1
    for (int it = 0; it < KV_NIT; it++) {
        cp_wait<KV_STAGES - 2>();
        __syncthreads();
        {
            const int sl = it + KV_STAGES - 1;
            if (sl < KV_NIT) {
                const int k0 = sl * 32;
                const int sb = sl % KV_STAGES;
                uint32_t aS = sbase + sb * KV_STAGE_BYTES;
                uint32_t bS = sB0 + sb * KV_STAGE_BYTES;
                cp_async16(aS + st_off,  g_cnb + (size_t)(n0 + ld_row) * CTXd + k0 + ld_col);
                cp_async16(aS + st_off2, g_cnb + (size_t)(n0 + ld_row + 64) * CTXd + k0 + ld_col);
                cp_async16(bS + st_off,  W + (size_t)(o0 + ld_row) * CTXd + k0 + ld_col);
                cp_async16(bS + st_off2, W + (size_t)(o0 + ld_row + 64) * CTXd + k0 + ld_col);
            }
            cp_commit();
        }

        const int sc = it % KV_STAGES;
        const uint32_t aBuf = sbase + sc * KV_STAGE_BYTES;
        const uint32_t bBuf = sB0 + sc * KV_STAGE_BYTES;

        #pragma unroll
        for (int kk = 0; kk < 2; kk++) {
            uint32_t af[4][4];
            #pragma unroll
            for (int mt = 0; mt < 4; mt++) {
                uint32_t addr = aBuf + a_lm_base + (mt * 16 * KVA_STR + kk * 16) * 2;
                asm volatile(
                    "ldmatrix.sync.aligned.m8n8.x4.shared.b16 {%0,%1,%2,%3}, [%4];"
                    : "=r"(af[mt][0]), "=r"(af[mt][1]), "=r"(af[mt][2]), "=r"(af[mt][3])
                    : "r"(addr));
            }
            uint32_t bf[4][2];
            #pragma unroll
            for (int nt = 0; nt < 4; nt++) {
                uint32_t addr = bBuf + b_lm_part +
                    (((wn * 32 + nt * 8) * KVA_STR) + kk * 16) * 2;
                asm volatile(
                    "ldmatrix.sync.aligned.m8n8.x2.shared.b16 {%0,%1}, [%2];"
                    : "=r"(bf[nt][0]), "=r"(bf[nt][1]) : "r"(addr));
            }
            #pragma unroll
            for (int mt = 0; mt < 4; mt++)
                #pragma unroll
                for (int nt = 0; nt < 4; nt++) {
                    asm volatile(
                        "mma.sync.aligned.m16n8k16.row.col.f32.bf16.bf16.f32 "
                        "{%0,%1,%2,%3}, {%4,%5,%6,%7}, {%8,%9}, {%0,%1,%2,%3};"
                        : "+f"(acc[mt][nt][0]), "+f"(acc[mt][nt][1]),
                          "+f"(acc[mt][nt][2]), "+f"(acc[mt][nt][3])
                        : "r"(af[mt][0]), "r"(af[mt][1]), "r"(af[mt][2]), "r"(af[mt][3]),
                          "r"(bf[nt][0]), "r"(bf[nt][1]));
                }
        }
    }

    const int row_base = n0 + wm * 64 + (lane >> 2);
    const int col_base = o0 + wn * 32 + (lane & 3) * 2;
    #pragma unroll
    for (int mt = 0; mt < 4; mt++) {
        #pragma unroll
        for (int half = 0; half < 2; half++) {
            int row = row_base + mt * 16 + half * 8;
            if (row >= NROWS) continue;
            #pragma unroll
            for (int nt = 0; nt < 4; nt++) {
                int col = col_base + nt * 8;
                float bi0 = bias[col], bi1 = bias[col + 1];
                *(__nv_bfloat162*)(out + (size_t)row * Cdim + col) =
                    __floats2bfloat162_rn(acc[mt][nt][half * 2] + bi0,
                                          acc[mt][nt][half * 2 + 1] + bi1);
            }
        }
    }
}

// ============================================================
// bf16 mma.sync GEMM — 128 thr / 4 warps, warp tile 64x64,
// B fragments via x4.trans ldmatrix. 4-stage cp.async pipeline.
// (4 stages = 75776 B/CTA keeps occupancy 2; 5 stages proven to
//  drop to occ 1 and regress 387->562 us.)
// ============================================================
#define A_STRIDE 40
#define B_STRIDE 136
#define STAGES 4
#define A_STAGE_BYTES (128 * A_STRIDE * 2)
#define B_STAGE_BYTES (32 * B_STRIDE * 2)
#define NIT (Cdim / 32)

template <bool BF16OUT>
__global__ void __launch_bounds__(128, 2)
mma_gemm(const __nv_bfloat16* __restrict__ Wb,
         const __nv_bfloat16* __restrict__ Xb,
         const float* __restrict__ bias,
         const float* __restrict__ residual,
         void* __restrict__ outv,
         int b0) {
    __shared__ __align__(16) char smem_[STAGES * (A_STAGE_BYTES + B_STAGE_BYTES)];

    const int tid  = threadIdx.x;
    const int warp = tid >> 5, lane = tid & 31;
    const int wm = warp >> 1, wn = warp & 1;
    const int p0 = blockIdx.x * 128;
    const int o0 = blockIdx.y * 128;
    const int b  = b0 + blockIdx.z;
    const __nv_bfloat16* Xbb = Xb + (size_t)b * Cdim * HWp;

    const uint32_t sbase = smem_u32(smem_);
    const uint32_t sB0 = sbase + STAGES * A_STAGE_BYTES;

    const int a_ld_row = tid >> 2;
    const int a_ld_col = (tid & 3) * 8;
    const int b_ld_row = tid >> 4;
    const int b_ld_col = (tid & 15) * 8;

    const uint32_t a_lm_base =
        ((wm * 64 + (lane & 15)) * A_STRIDE + (lane >> 4) * 8) * 2;
    const uint32_t b_lm4_base =
        (((lane & 7) + ((lane >> 3) & 1) * 8) * B_STRIDE +
         wn * 64 + ((lane >> 4) & 1) * 8) * 2;

    uint32_t a_st[4], b_st[4];
    #pragma unroll
    for (int j = 0; j < 4; j++) {
        a_st[j] = ((a_ld_row + j * 32) * A_STRIDE + a_ld_col) * 2;
        b_st[j] = ((b_ld_row + j * 8) * B_STRIDE + b_ld_col) * 2;
    }

    float acc[4][8][4] = {};

    #pragma unroll
    for (int s = 0; s < STAGES - 1; s++) {
        const int k0 = s * 32;
        uint32_t aS = sbase + s * A_STAGE_BYTES;
        uint32_t bS = sB0 + s * B_STAGE_BYTES;
        #pragma unroll
        for (int j = 0; j < 4; j++) {
            cp_async16(aS + a_st[j],
                       Wb + (size_t)(o0 + a_ld_row + j * 32) * Cdim + k0 + a_ld_col);
            cp_async16(bS + b_st[j],
                       Xbb + (size_t)(k0 + b_ld_row + j * 8) * HWp + p0 + b_ld_col);
        }
        cp_commit();
    }

    #pragma unroll 1
    for (int it = 0; it < NIT; it++) {
        cp_wait<STAGES - 2>();
        __syncthreads();
        {
            const int sl = it + STAGES - 1;
            if (sl < NIT) {
                const int k0 = sl * 32;
                const int sb = sl % STAGES;
                uint32_t aS = sbase + sb * A_STAGE_BYTES;
                uint32_t bS = sB0 + sb * B_STAGE_BYTES;
                #pragma unroll
                for (int j = 0; j < 4; j++) {
                    cp_async16(aS + a_st[j],
                               Wb + (size_t)(o0 + a_ld_row + j * 32) * Cdim + k0 + a_ld_col);
                    cp_async16(bS + b_st[j],
                               Xbb + (size_t)(k0 + b_ld_row + j * 8) * HWp + p0 + b_ld_col);
                }
            }
            cp_commit();
        }

        const int sc = it % STAGES;
        const uint32_t aBuf = sbase + sc * A_STAGE_BYTES;
        const uint32_t bBuf = sB0 + sc * B_STAGE_BYTES;

        #pragma unroll
        for (int kk = 0; kk < 2; kk++) {
            uint32_t af[4][4];
            #pragma unroll
            for (int mt = 0; mt < 4; mt++) {
                uint32_t addr = aBuf + a_lm_base + (mt * 16 * A_STRIDE + kk * 16) * 2;
                asm volatile(
                    "ldmatrix.sync.aligned.m8n8.x4.shared.b16 {%0,%1,%2,%3}, [%4];"
                    : "=r"(af[mt][0]), "=r"(af[mt][1]), "=r"(af[mt][2]), "=r"(af[mt][3])
                    : "r"(addr));
            }
            uint32_t bf[8][2];
            #pragma unroll
            for (int ntp = 0; ntp < 4; ntp++) {
                uint32_t addr = bBuf + b_lm4_base +
                    (kk * 16 * B_STRIDE + ntp * 16) * 2;
                asm volatile(
                    "ldmatrix.sync.aligned.m8n8.x4.trans.shared.b16 {%0,%1,%2,%3}, [%4];"
                    : "=r"(bf[2 * ntp][0]), "=r"(bf[2 * ntp][1]),
                      "=r"(bf[2 * ntp + 1][0]), "=r"(bf[2 * ntp + 1][1])
                    : "r"(addr));
            }
            #pragma unroll
            for (int mt = 0; mt < 4; mt++)
                #pragma unroll
                for (int nt = 0; nt < 8; nt++) {
                    asm volatile(
                        "mma.sync.aligned.m16n8k16.row.col.f32.bf16.bf16.f32 "
                        "{%0,%1,%2,%3}, {%4,%5,%6,%7}, {%8,%9}, {%0,%1,%2,%3};"
                        : "+f"(acc[mt][nt][0]), "+f"(acc[mt][nt][1]),
                          "+f"(acc[mt][nt][2]), "+f"(acc[mt][nt][3])
                        : "r"(af[mt][0]), "r"(af[mt][1]), "r"(af[mt][2]), "r"(af[mt][3]),
                          "r"(bf[nt][0]), "r"(bf[nt][1]));
                }
        }
    }

    const int row_base = o0 + wm * 64 + (lane >> 2);
    const int col_base = p0 + wn * 64 + (lane & 3) * 2;
    #pragma unroll
    for (int mt = 0; mt < 4; mt++) {
        #pragma unroll
        for (int half = 0; half < 2; half++) {
            int row = row_base + mt * 16 + half * 8;
            float bi = bias[row];
            size_t rb = ((size_t)b * Cdim + row) * HWp;
            #pragma unroll
            for (int nt = 0; nt < 8; nt++) {
                int col = col_base + nt * 8;
                float rx = acc[mt][nt][half * 2]     + bi;
                float ry = acc[mt][nt][half * 2 + 1] + bi;
                if (BF16OUT) {
                    __nv_bfloat16* outb = (__nv_bfloat16*)outv;
                    *(__nv_bfloat162*)(outb + rb + col) = __floats2bfloat162_rn(rx, ry);
                } else {
                    float* outf = (float*)outv;
                    if (residual) {
                        float2 rv = *(const float2*)(residual + rb + col);
                        rx += rv.x; ry += rv.y;
                    }
                    float2 r; r.x = rx; r.y = ry;
                    *(float2*)(outf + rb + col) = r;
                }
            }
        }
    }
}

// ============================================================
// Tensor-core flash attention — monolithic
// ============================================================
#define QS_STR 136
#define KS_STR 72
#define SPAD 80

__global__ void __launch_bounds__(128)
attn_mma_kernel() {
    __shared__ __align__(16) __nv_bfloat16 sQ[64 * QS_STR];
    __shared__ __align__(16) __nv_bfloat16 sK[SPAD * KS_STR];
    __shared__ __align__(16) __nv_bfloat16 sV[SPAD * KS_STR];

    const int tid = threadIdx.x;
    const int warp = tid >> 5, lane = tid & 31;
    const int b = blockIdx.z, h = blockIdx.y;
    const int p0 = blockIdx.x * 128;
    const int ch0 = h * HD;

    const __nv_bfloat16* qg = g_qb + ((size_t)b * Cdim + ch0) * HWp + p0;
    #pragma unroll 4
    for (int i = tid; i < 64 * 16; i += 128) {
        int d = i >> 4, cc = (i & 15) * 8;
        *(uint4*)(sQ + d * QS_STR + cc) = *(const uint4*)(qg + (size_t)d * HWp + cc);
    }
    const __nv_bfloat16* kg = g_kb + (size_t)b * Sctx * Cdim + ch0;
    for (int i = tid; i < 77 * 8; i += 128) {
        int s = i >> 3, dd = (i & 7) * 8;
        *(uint4*)(sK + s * KS_STR + dd) = *(const uint4*)(kg + (size_t)s * Cdim + dd);
    }
    if (tid < 24) {
        int s = 77 + tid / 8, dd = (tid & 7) * 8;
        uint4 z = {0, 0, 0, 0};
        *(uint4*)(sK + s * KS_STR + dd) = z;
    }
    const __nv_bfloat16* vg = g_vb + (size_t)b * Sctx * Cdim + ch0;
    for (int i = tid; i < 77 * 8; i += 128) {
        int s = i >> 3, dd = (i & 7) * 8;
        *(uint4*)(sV + s * KS_STR + dd) = *(const uint4*)(vg + (size_t)s * Cdim + dd);
    }
    if (tid >= 104) {
        int t = tid - 104;
        int s = 77 + t / 8, dd = (t & 7) * 8;
        uint4 z = {0, 0, 0, 0};
        *(uint4*)(sV + s * KS_STR + dd) = z;
    }
    __syncthreads();

    const uint32_t qbase = smem_u32(sQ);
    const uint32_t kbase = smem_u32(sK);
    const uint32_t vbase = smem_u32(sV);

    float c[2][10][4];
    #pragma unroll
    for (int mt = 0; mt < 2; mt++)
        #pragma unroll
        for (int nt = 0; nt < 10; nt++)
            #pragma unroll
            for (int r = 0; r < 4; r++) c[mt][nt][r] = 0.f;

    const int a_krow = ((lane >> 4) & 1) * 8 + (lane & 7);
    const int a_mcol = ((lane >> 3) & 1) * 8;
    const uint32_t b_lm_part = ((lane & 7) * KS_STR + ((lane >> 3) & 1) * 8) * 2;

    #pragma unroll
    for (int kk = 0; kk < 4; kk++) {
        uint32_t af[2][4];
        #pragma unroll
        for (int mt = 0; mt < 2; mt++) {
            uint32_t addr = qbase +
                ((kk * 16 + a_krow) * QS_STR + warp * 32 + mt * 16 + a_mcol) * 2;
            asm volatile(
                "ldmatrix.sync.aligned.m8n8.x4.trans.shared.b16 {%0,%1,%2,%3}, [%4];"
                : "=r"(af[mt][0]), "=r"(af[mt][1]), "=r"(af[mt][2]), "=r"(af[mt][3])
                : "r"(addr));
        }
        uint32_t bf[10][2];
        #pragma unroll
        for (int nt = 0; nt < 10; nt++) {
            uint32_t addr = kbase + b_lm_part + ((nt * 8) * KS_STR + kk * 16) * 2;
            asm volatile(
                "ldmatrix.sync.aligned.m8n8.x2.shared.b16 {%0,%1}, [%2];"
                : "=r"(bf[nt][0]), "=r"(bf[nt][1]) : "r"(addr));
        }
        #pragma unroll
        for (int mt = 0; mt < 2; mt++)
            #pragma unroll
            for (int nt = 0; nt < 10; nt++) {
                asm volatile(
                    "mma.sync.aligned.m16n8k16.row.col.f32.bf16.bf16.f32 "
                    "{%0,%1,%2,%3}, {%4,%5,%6,%7}, {%8,%9}, {%0,%1,%2,%3};"
                    : "+f"(c[mt][nt][0]), "+f"(c[mt][nt][1]),
                      "+f"(c[mt][nt][2]), "+f"(c[mt][nt][3])
                    : "r"(af[mt][0]), "r"(af[mt][1]), "r"(af[mt][2]), "r"(af[mt][3]),
                      "r"(bf[nt][0]), "r"(bf[nt][1]));
            }
    }
    __syncthreads();

    const float scale = 0.125f;
    uint32_t pu[2][10][2];
    float iv[2][2];
    #pragma unroll
    for (int mt = 0; mt < 2; mt++) {
        float mx0 = -1e30f, mx1 = -1e30f;
        #pragma unroll
        for (int nt = 0; nt < 10; nt++) {
            int col = nt * 8 + (lane & 3) * 2;
            c[mt][nt][0] = (col     < Sctx) ? c[mt][nt][0] * scale : -1e30f;
            c[mt][nt][1] = (col + 1 < Sctx) ? c[mt][nt][1] * scale : -1e30f;
            c[mt][nt][2] = (col     < Sctx) ? c[mt][nt][2] * scale : -1e30f;
            c[mt][nt][3] = (col + 1 < Sctx) ? c[mt][nt][3] * scale : -1e30f;
            mx0 = fmaxf(mx0, fmaxf(c[mt][nt][0], c[mt][nt][1]));
            mx1 = fmaxf(mx1, fmaxf(c[mt][nt][2], c[mt][nt][3]));
        }
        mx0 = fmaxf(mx0, __shfl_xor_sync(0xffffffffu, mx0, 1));
        mx0 = fmaxf(mx0, __shfl_xor_sync(0xffffffffu, mx0, 2));
        mx1 = fmaxf(mx1, __shfl_xor_sync(0xffffffffu, mx1, 1));
        mx1 = fmaxf(mx1, __shfl_xor_sync(0xffffffffu, mx1, 2));
        float s0 = 0.f, s1 = 0.f;
        #pragma unroll
        for (int nt = 0; nt < 10; nt++) {
            float e0 = __expf(c[mt][nt][0] - mx0);
            float e1 = __expf(c[mt][nt][1] - mx0);
            float e2 = __expf(c[mt][nt][2] - mx1);
            float e3 = __expf(c[mt][nt][3] - mx1);
            s0 += e0 + e1; s1 += e2 + e3;
            pu[mt][nt][0] = pack_bf16(e0, e1);
            pu[mt][nt][1] = pack_bf16(e2, e3);
        }
        s0 += __shfl_xor_sync(0xffffffffu, s0, 1);
        s0 += __shfl_xor_sync(0xffffffffu, s0, 2);
        s1 += __shfl_xor_sync(0xffffffffu, s1, 1);
        s1 += __shfl_xor_sync(0xffffffffu, s1, 2);
        iv[mt][0] = 1.f / s0;
        iv[mt][1] = 1.f / s1;
    }

    float o[2][8][4];
    #pragma unroll
    for (int mt = 0; mt < 2; mt++)
        #pragma unroll
        for (int nt = 0; nt < 8; nt++)
            #pragma unroll
            for (int r = 0; r < 4; r++) o[mt][nt][r] = 0.f;

    #pragma unroll
    for (int kk = 0; kk < 5; kk++) {
        uint32_t bv[8][2];
        #pragma unroll
        for (int nt = 0; nt < 8; nt++) {
            uint32_t addr = vbase + ((kk * 16 + (lane & 15)) * KS_STR + nt * 8) * 2;
            asm volatile(
                "ldmatrix.sync.aligned.m8n8.x2.trans.shared.b16 {%0,%1}, [%2];"
                : "=r"(bv[nt][0]), "=r"(bv[nt][1]) : "r"(addr));
        }
        #pragma unroll
        for (int mt = 0; mt < 2; mt++) {
            uint32_t a0 = pu[mt][2 * kk][0];
            uint32_t a1 = pu[mt][2 * kk][1];
            uint32_t a2 = pu[mt][2 * kk + 1][0];
            uint32_t a3 = pu[mt][2 * kk + 1][1];
            #pragma unroll
            for (int nt = 0; nt < 8; nt++) {
                asm volatile(
                    "mma.sync.aligned.m16n8k16.row.col.f32.bf16.bf16.f32 "
                    "{%0,%1,%2,%3}, {%4,%5,%6,%7}, {%8,%9}, {%0,%1,%2,%3};"
                    : "+f"(o[mt][nt][0]), "+f"(o[mt][nt][1]),
                      "+f"(o[mt][nt][2]), "+f"(o[mt][nt][3])
                    : "r"(a0), "r"(a1), "r"(a2), "r"(a3),
                      "r"(bv[nt][0]), "r"(bv[nt][1]));
            }
        }
    }

    __nv_bfloat16* Od = sQ;
    #pragma unroll
    for (int mt = 0; mt < 2; mt++) {
        int pxa = warp * 32 + mt * 16 + (lane >> 2);
        #pragma unroll
        for (int nt = 0; nt < 8; nt++) {
            int d = nt * 8 + (lane & 3) * 2;
            Od[d * QS_STR + pxa]           = __float2bfloat16(o[mt][nt][0] * iv[mt][0]);
            Od[(d + 1) * QS_STR + pxa]     = __float2bfloat16(o[mt][nt][1] * iv[mt][0]);
            Od[d * QS_STR + pxa + 8]       = __float2bfloat16(o[mt][nt][2] * iv[mt][1]);
            Od[(d + 1) * QS_STR + pxa + 8] = __float2bfloat16(o[mt][nt][3] * iv[mt][1]);
        }
    }
    __syncthreads();

    __nv_bfloat16* og = g_aob + ((size_t)b * Cdim + ch0) * HWp + p0;
    #pragma unroll 2
    for (int i = tid; i < 64 * 16; i += 128) {
        int d = i >> 4, cc = (i & 15) * 8;
        *(uint4*)(og + (size_t)d * HWp + cc) = *(const uint4*)(Od + d * QS_STR + cc);
    }
}

// ============================================================
extern "C" void kernel_launch(void* const* d_in, const int* in_sizes, int n_in,
                              void* d_out, int out_size) {
    const float* x       = (const float*)d_in[0];
    const float* context = (const float*)d_in[1];
    const float* gn_w    = (const float*)d_in[2];
    const float* gn_b    = (const float*)d_in[3];
    const float* ln_w    = (const float*)d_in[4];
    const float* ln_b    = (const float*)d_in[5];
    const float* q_w     = (const float*)d_in[6];
    const float* q_b     = (const float*)d_in[7];
    const float* k_w     = (const float*)d_in[8];
    const float* k_b     = (const float*)d_in[9];
    const float* v_w     = (const float*)d_in[10];
    const float* v_b     = (const float*)d_in[11];
    const float* out_w   = (const float*)d_in[12];
    const float* out_b   = (const float*)d_in[13];
    float* out = (float*)d_out;

    __nv_bfloat16 *qb = nullptr, *xnb = nullptr, *aob = nullptr, *qwb = nullptr, *owb = nullptr;
    cudaGetSymbolAddress((void**)&qb,  g_qb);
    cudaGetSymbolAddress((void**)&xnb, g_xnb);
    cudaGetSymbolAddress((void**)&aob, g_aob);
    cudaGetSymbolAddress((void**)&qwb, g_qwb);
    cudaGetSymbolAddress((void**)&owb, g_owb);

    // one-time side stream + events (created on the uncaptured correctness call)
    static cudaStream_t s_side = nullptr;
    static cudaEvent_t ev_fork = nullptr, ev_w = nullptr, ev_kv = nullptr;
    if (s_side == nullptr) {
        cudaStreamCreateWithFlags(&s_side, cudaStreamNonBlocking);
        cudaEventCreateWithFlags(&ev_fork, cudaEventDisableTiming);
        cudaEventCreateWithFlags(&ev_w,    cudaEventDisableTiming);
        cudaEventCreateWithFlags(&ev_kv,   cudaEventDisableTiming);
    }

    // fork side stream
    cudaEventRecord(ev_fork, 0);
    cudaStreamWaitEvent(s_side, ev_fork, 0);

    // side chain: weights -> ln -> kv
    conv_w_kernel<<<(2 * NQW + 2 * NKW) / 512, 512, 0, s_side>>>(q_w, out_w, k_w, v_w);
    cudaEventRecord(ev_w, s_side);
    ln_kernel<<<Bsz * Sctx, 256, 0, s_side>>>(context, ln_w, ln_b);
    kv_mma<<<dim3(Cdim / 128, NROWS_PAD / 128, 2), 256, 0, s_side>>>(k_b, v_b);
    cudaEventRecord(ev_kv, s_side);

    // main chain: gn (monolithic) -> qproj -> attn -> outproj
    gn_fuse_kernel<<<Bsz * NGROUPS, 512>>>(x, gn_w, gn_b);
    cudaStreamWaitEvent(0, ev_w, 0);
    mma_gemm<true><<<dim3(HWp / 128, Cdim / 128, Bsz), 128>>>(
        qwb, xnb, q_b, nullptr, qb, 0);
    cudaStreamWaitEvent(0, ev_kv, 0);
    attn_mma_kernel<<<dim3(HWp / 128, NHEADS, Bsz), 128>>>();
    mma_gemm<false><<<dim3(HWp / 128, Cdim / 128, Bsz), 128>>>(
        owb, aob, out_b, x, out, 0);
}